// round 8
// baseline (speedup 1.0000x reference)
#include <cuda_runtime.h>
#include <cuda_fp16.h>
#include <cstdint>

// Problem constants
#define E_   8
#define T_   1024
#define H_   1024
#define F_   4096
#define DL_  256
#define NTOK (E_ * T_)   // 8192

// ---------------- device scratch ----------------
__device__ __half g_x  [(size_t)NTOK * H_];
__device__ __half g_a  [(size_t)NTOK * DL_];
__device__ __half g_wup[(size_t)E_ * F_ * DL_];
__device__ __half g_v1 [(size_t)E_ * F_ * H_];
__device__ __half g_h  [(size_t)E_ * T_ * F_];
__device__ __half g_w2t[(size_t)E_ * H_ * F_];

// ---------------- helpers ----------------
__device__ __forceinline__ uint32_t smem_u32(const void* p) {
    uint32_t a;
    asm("{ .reg .u64 t; cvta.to.shared.u64 t, %1; cvt.u32.u64 %0, t; }" : "=r"(a) : "l"(p));
    return a;
}
__device__ __forceinline__ void ldsm_x4(uint32_t (&r)[4], uint32_t addr) {
    asm volatile("ldmatrix.sync.aligned.m8n8.x4.shared.b16 {%0,%1,%2,%3}, [%4];"
        : "=r"(r[0]), "=r"(r[1]), "=r"(r[2]), "=r"(r[3]) : "r"(addr));
}
__device__ __forceinline__ void mma16816(float (&d)[4], const uint32_t (&a)[4],
                                         uint32_t b0, uint32_t b1) {
    asm volatile(
        "mma.sync.aligned.m16n8k16.row.col.f32.f16.f16.f32 "
        "{%0,%1,%2,%3}, {%4,%5,%6,%7}, {%8,%9}, {%0,%1,%2,%3};"
        : "+f"(d[0]), "+f"(d[1]), "+f"(d[2]), "+f"(d[3])
        : "r"(a[0]), "r"(a[1]), "r"(a[2]), "r"(a[3]), "r"(b0), "r"(b1));
}
__device__ __forceinline__ void cp16(uint32_t saddr, const void* g) {
    asm volatile("cp.async.cg.shared.global [%0], [%1], 16;" :: "r"(saddr), "l"(g));
}
#define CP_COMMIT() asm volatile("cp.async.commit_group;" ::: "memory")
#define CP_WAIT(N)  asm volatile("cp.async.wait_group %0;" :: "n"(N) : "memory")

__device__ __forceinline__ uint32_t pack_h2(__half a, __half b) {
    __half2 t; t.x = a; t.y = b;
    return *reinterpret_cast<uint32_t*>(&t);
}
__device__ __forceinline__ float silu(float a) { return a / (1.0f + __expf(-a)); }

// ---------------- fused conversion kernel (x, acts, wup, v1) ----------------
static constexpr size_t CB0 = (size_t)NTOK * H_ / 8;
static constexpr size_t CB1 = CB0 + (size_t)NTOK * DL_ / 8;
static constexpr size_t CB2 = CB1 + (size_t)E_ * F_ * DL_ / 8;
static constexpr size_t CB3 = CB2 + (size_t)E_ * F_ * H_ / 8;

__global__ void __launch_bounds__(256) conv_all(const float* __restrict__ x,
                                                const float* __restrict__ a,
                                                const float* __restrict__ w,
                                                const float* __restrict__ v) {
    size_t it = (size_t)blockIdx.x * 256 + threadIdx.x;
    const float* s; __half* d; size_t off;
    if      (it < CB0) { s = x; d = g_x;   off = it; }
    else if (it < CB1) { s = a; d = g_a;   off = it - CB0; }
    else if (it < CB2) { s = w; d = g_wup; off = it - CB1; }
    else               { s = v; d = g_v1;  off = it - CB2; }
    size_t i = off * 8;
    float4 v0 = *reinterpret_cast<const float4*>(s + i);
    float4 v1 = *reinterpret_cast<const float4*>(s + i + 4);
    uint4 o;
    o.x = pack_h2(__float2half_rn(v0.x), __float2half_rn(v0.y));
    o.y = pack_h2(__float2half_rn(v0.z), __float2half_rn(v0.w));
    o.z = pack_h2(__float2half_rn(v1.x), __float2half_rn(v1.y));
    o.w = pack_h2(__float2half_rn(v1.z), __float2half_rn(v1.w));
    *reinterpret_cast<uint4*>(d + i) = o;
}

// w2 [E,F,H] -> w2t [E,H,F] fp16, coalesced half2 stores
__global__ void __launch_bounds__(256) transpose_convert_w2(const float* __restrict__ w2) {
    __shared__ float tile[64][33];
    int e = blockIdx.z;
    int f0 = blockIdx.x * 64, h0 = blockIdx.y * 32;
    int tx = threadIdx.x, ty = threadIdx.y;  // 32 x 8
#pragma unroll
    for (int r = 0; r < 8; r++) {
        int fr = ty + r * 8;
        tile[fr][tx] = w2[((size_t)e * F_ + f0 + fr) * H_ + h0 + tx];
    }
    __syncthreads();
#pragma unroll
    for (int r = 0; r < 4; r++) {
        int h = ty + r * 8;
        uint32_t p = pack_h2(__float2half_rn(tile[2 * tx][h]),
                             __float2half_rn(tile[2 * tx + 1][h]));
        *reinterpret_cast<uint32_t*>(&g_w2t[((size_t)e * H_ + h0 + h) * F_ + f0 + 2 * tx]) = p;
    }
}

// ================= shared GEMM pieces: CTA 128(m) x 256(n), 512 thr, warp 32x64 =================
static constexpr int SA64 = 72;                    // row stride (fp16), 144 B
static constexpr int A_BYTES = 128 * SA64 * 2;     // 18432
static constexpr int B_BYTES = 256 * SA64 * 2;     // 36864
static constexpr int STG   = A_BYTES + B_BYTES;    // 55296
static constexpr int SMEMB = 3 * STG;              // 165888
static constexpr int NWORK = 148;

// load ROWSx64 fp16 K-major tile; 512 threads, 16B chunks
template <int ROWS>
__device__ __forceinline__ void load_rows(uint32_t sdst, const __half* __restrict__ g,
                                          int ldg, int tid) {
#pragma unroll
    for (int i = 0; i < ROWS * 8 / 512; i++) {
        int c = tid + i * 512;
        int row = c >> 3, col = (c & 7) * 8;
        cp16(sdst + (uint32_t)(row * SA64 + col) * 2, g + (size_t)row * ldg + col);
    }
}

// one K=64 stage for a 32x64 warp tile, with register-fragment double buffering:
// ldsm for the NEXT group issues before the MMAs of the current group consume theirs,
// so the ~29cyc LDS latency hides under 4 MMAs.
__device__ __forceinline__ void mma_3264(float (&acc)[2][8][4], uint32_t sb,
                                         int warp_m, int warp_n, int lane) {
    uint32_t sA = sb, sB = sb + A_BYTES;
    int lrow = lane & 15, lk = (lane >> 4) * 8;
    uint32_t abase = sA + (uint32_t)((warp_m * 32 + lrow) * SA64 + lk) * 2;
    uint32_t bbase = sB + (uint32_t)((warp_n * 64 + lrow) * SA64 + lk) * 2;
    constexpr uint32_t R16 = 16 * SA64 * 2;   // 16-row stride in bytes

    uint32_t a[2][2][4], b[2][4];
    ldsm_x4(a[0][0], abase);
    ldsm_x4(a[0][1], abase + R16);
    ldsm_x4(b[0], bbase);
#pragma unroll
    for (int ks = 0; ks < 4; ks++) {
        const int ap = ks & 1;
#pragma unroll
        for (int gj = 0; gj < 4; gj++) {
            const int bp = (ks * 4 + gj) & 1;
            // prefetch next fragments (compile-time predicates; loops fully unrolled)
            if (gj == 0 && ks < 3) ldsm_x4(a[ap ^ 1][0], abase + (ks + 1) * 32);
            if (gj == 1 && ks < 3) ldsm_x4(a[ap ^ 1][1], abase + (ks + 1) * 32 + R16);
            if (gj < 3)            ldsm_x4(b[bp ^ 1], bbase + ks * 32 + (gj + 1) * R16);
            else if (ks < 3)       ldsm_x4(b[bp ^ 1], bbase + (ks + 1) * 32);
            mma16816(acc[0][gj * 2 + 0], a[ap][0], b[bp][0], b[bp][2]);
            mma16816(acc[0][gj * 2 + 1], a[ap][0], b[bp][1], b[bp][3]);
            mma16816(acc[1][gj * 2 + 0], a[ap][1], b[bp][0], b[bp][2]);
            mma16816(acc[1][gj * 2 + 1], a[ap][1], b[bp][1], b[bp][3]);
        }
    }
}

// ================= GLU persistent: tile 128x256 =================
static constexpr int NT_GLU = (T_ / 128) * (F_ / 256) * E_;   // 1024
static constexpr int NKC_GLU = 4 + 16;                        // acts/wup then x/v1

__global__ void __launch_bounds__(512, 1) glu_kernel() {
    extern __shared__ char smem[];
    uint32_t sbase = smem_u32(smem);
    int tid = threadIdx.x, lane = tid & 31, wid = tid >> 5;
    int warp_m = wid & 3, warp_n = wid >> 2;   // 4 x 4
    int bid = blockIdx.x;

    // loader state (2 chunks ahead, flat stream across tiles)
    int lt = bid, lk = 0, ls = 0;
    const __half *LAa, *LBw, *LAx, *LBv;
    auto set_lptrs = [&](int t) {
        int e = t >> 7, r = t & 127;
        int m0 = (r >> 4) * 128, f0 = (r & 15) * 256;
        LAa = g_a   + (size_t)(e * T_ + m0) * DL_;
        LBw = g_wup + ((size_t)e * F_ + f0) * DL_;
        LAx = g_x   + (size_t)(e * T_ + m0) * H_;
        LBv = g_v1  + ((size_t)e * F_ + f0) * H_;
    };
    if (lt < NT_GLU) set_lptrs(lt);
    auto issue = [&]() {
        uint32_t sb = sbase + ls * STG;
        if (lt < NT_GLU) {
            if (lk < 4) {
                load_rows<128>(sb,           LAa + lk * 64, DL_, tid);
                load_rows<256>(sb + A_BYTES, LBw + lk * 64, DL_, tid);
            } else {
                int k2 = lk - 4;
                load_rows<128>(sb,           LAx + k2 * 64, H_, tid);
                load_rows<256>(sb + A_BYTES, LBv + k2 * 64, H_, tid);
            }
        }
        CP_COMMIT();   // empty group past end keeps wait counts uniform
        if (++ls == 3) ls = 0;
        if (++lk == NKC_GLU) { lk = 0; lt += NWORK; if (lt < NT_GLU) set_lptrs(lt); }
    };
    issue(); issue();

    int cs = 0;
    for (int ct = bid; ct < NT_GLU; ct += NWORK) {
        int e = ct >> 7, r = ct & 127;
        int m0 = (r >> 4) * 128, f0 = (r & 15) * 256;

        float acc[2][8][4];
        uint32_t x1h[2][8][2];   // packed x1 (phase A result)
#pragma unroll
        for (int i = 0; i < 2; i++)
#pragma unroll
            for (int j = 0; j < 8; j++)
#pragma unroll
                for (int k = 0; k < 4; k++) acc[i][j][k] = 0.f;

        for (int kt = 0; kt < NKC_GLU; kt++) {
            CP_WAIT(1);
            __syncthreads();
            issue();
            if (kt == 4) {
                // phase A done: pack x1 to fp16, reset acc for phase B
#pragma unroll
                for (int mi = 0; mi < 2; mi++)
#pragma unroll
                for (int nj = 0; nj < 8; nj++) {
                    x1h[mi][nj][0] = pack_h2(__float2half_rn(acc[mi][nj][0]),
                                             __float2half_rn(acc[mi][nj][1]));
                    x1h[mi][nj][1] = pack_h2(__float2half_rn(acc[mi][nj][2]),
                                             __float2half_rn(acc[mi][nj][3]));
                    acc[mi][nj][0] = 0.f; acc[mi][nj][1] = 0.f;
                    acc[mi][nj][2] = 0.f; acc[mi][nj][3] = 0.f;
                }
            }
            mma_3264(acc, sbase + cs * STG, warp_m, warp_n, lane);
            if (++cs == 3) cs = 0;
        }

        // epilogue: h = silu(x1) * acc2 -> fp16 (overlaps next tile's loads)
        int gid = lane >> 2, q = lane & 3;
#pragma unroll
        for (int mi = 0; mi < 2; mi++)
#pragma unroll
        for (int nj = 0; nj < 8; nj++) {
            int m = m0 + warp_m * 32 + mi * 16 + gid;
            int n = f0 + warp_n * 64 + nj * 8 + q * 2;
            __half2 p0 = *reinterpret_cast<__half2*>(&x1h[mi][nj][0]);
            __half2 p1 = *reinterpret_cast<__half2*>(&x1h[mi][nj][1]);
            float s0 = silu(__half2float(p0.x)) * acc[mi][nj][0];
            float s1 = silu(__half2float(p0.y)) * acc[mi][nj][1];
            float s2 = silu(__half2float(p1.x)) * acc[mi][nj][2];
            float s3 = silu(__half2float(p1.y)) * acc[mi][nj][3];
            size_t off0 = ((size_t)(e * T_ + m)) * F_ + n;
            size_t off1 = ((size_t)(e * T_ + m + 8)) * F_ + n;
            *reinterpret_cast<uint32_t*>(g_h + off0) = pack_h2(__float2half_rn(s0), __float2half_rn(s1));
            *reinterpret_cast<uint32_t*>(g_h + off1) = pack_h2(__float2half_rn(s2), __float2half_rn(s3));
        }
    }
}

// ================= GEMM3 persistent: tile 128x256, K=4096 =================
static constexpr int NT_G3  = (T_ / 128) * (H_ / 256) * E_;  // 256
static constexpr int NKC_G3 = F_ / 64;                       // 64

__global__ void __launch_bounds__(512, 1) gemm3_kernel(float* __restrict__ out) {
    extern __shared__ char smem[];
    uint32_t sbase = smem_u32(smem);
    int tid = threadIdx.x, lane = tid & 31, wid = tid >> 5;
    int warp_m = wid & 3, warp_n = wid >> 2;   // 4 x 4
    int bid = blockIdx.x;

    int lt = bid, lk = 0, ls = 0;
    const __half *LA, *LB;
    auto set_lptrs = [&](int t) {
        int e = t >> 5, r = t & 31;
        int m0 = (r >> 2) * 128, n0 = (r & 3) * 256;
        LA = g_h   + (size_t)(e * T_ + m0) * F_;
        LB = g_w2t + ((size_t)e * H_ + n0) * F_;
    };
    if (lt < NT_G3) set_lptrs(lt);
    auto issue = [&]() {
        uint32_t sb = sbase + ls * STG;
        if (lt < NT_G3) {
            load_rows<128>(sb,           LA + lk * 64, F_, tid);
            load_rows<256>(sb + A_BYTES, LB + lk * 64, F_, tid);
        }
        CP_COMMIT();
        if (++ls == 3) ls = 0;
        if (++lk == NKC_G3) { lk = 0; lt += NWORK; if (lt < NT_G3) set_lptrs(lt); }
    };
    issue(); issue();

    int cs = 0;
    for (int ct = bid; ct < NT_G3; ct += NWORK) {
        int e = ct >> 5, r = ct & 31;
        int m0 = (r >> 2) * 128, n0 = (r & 3) * 256;

        float acc[2][8][4];
#pragma unroll
        for (int i = 0; i < 2; i++)
#pragma unroll
            for (int j = 0; j < 8; j++)
#pragma unroll
                for (int k = 0; k < 4; k++) acc[i][j][k] = 0.f;

        for (int kt = 0; kt < NKC_G3; kt++) {
            CP_WAIT(1);
            __syncthreads();
            issue();
            mma_3264(acc, sbase + cs * STG, warp_m, warp_n, lane);
            if (++cs == 3) cs = 0;
        }

        int gid = lane >> 2, q = lane & 3;
#pragma unroll
        for (int mi = 0; mi < 2; mi++)
#pragma unroll
        for (int nj = 0; nj < 8; nj++) {
            int m = m0 + warp_m * 32 + mi * 16 + gid;
            int n = n0 + warp_n * 64 + nj * 8 + q * 2;
            size_t off0 = ((size_t)(e * T_ + m)) * H_ + n;
            size_t off1 = ((size_t)(e * T_ + m + 8)) * H_ + n;
            *reinterpret_cast<float2*>(out + off0) = make_float2(acc[mi][nj][0], acc[mi][nj][1]);
            *reinterpret_cast<float2*>(out + off1) = make_float2(acc[mi][nj][2], acc[mi][nj][3]);
        }
    }
}

// ---------------- launch ----------------
extern "C" void kernel_launch(void* const* d_in, const int* in_sizes, int n_in,
                              void* d_out, int out_size) {
    const float* x    = (const float*)d_in[0];  // [8192, 1024]
    const float* acts = (const float*)d_in[1];  // [8192, 256]
    const float* wup  = (const float*)d_in[2];  // [8, 4096, 256]
    const float* v1   = (const float*)d_in[3];  // [8, 4096, 1024]
    const float* w2   = (const float*)d_in[4];  // [8, 4096, 1024]
    float* out = (float*)d_out;                 // [8192, 1024]

    cudaFuncSetAttribute(glu_kernel,   cudaFuncAttributeMaxDynamicSharedMemorySize, SMEMB);
    cudaFuncSetAttribute(gemm3_kernel, cudaFuncAttributeMaxDynamicSharedMemorySize, SMEMB);

    conv_all<<<(int)(CB3 / 256), 256>>>(x, acts, wup, v1);
    {
        dim3 tg(F_ / 64, H_ / 32, E_);
        transpose_convert_w2<<<tg, dim3(32, 8)>>>(w2);
    }
    glu_kernel<<<NWORK, 512, SMEMB>>>();
    gemm3_kernel<<<NWORK, 512, SMEMB>>>(out);
}

// round 10
// speedup vs baseline: 1.0011x; 1.0011x over previous
#include <cuda_runtime.h>
#include <cuda_fp16.h>
#include <cstdint>

// Problem constants
#define E_   8
#define T_   1024
#define H_   1024
#define F_   4096
#define DL_  256
#define NTOK (E_ * T_)   // 8192

// ---------------- device scratch ----------------
__device__ __half g_x  [(size_t)NTOK * H_];
__device__ __half g_a  [(size_t)NTOK * DL_];
__device__ __half g_wup[(size_t)E_ * F_ * DL_];
__device__ __half g_v1 [(size_t)E_ * F_ * H_];
__device__ __half g_h  [(size_t)E_ * T_ * F_];
__device__ __half g_w2t[(size_t)E_ * H_ * F_];

// ---------------- helpers ----------------
__device__ __forceinline__ uint32_t smem_u32(const void* p) {
    uint32_t a;
    asm("{ .reg .u64 t; cvta.to.shared.u64 t, %1; cvt.u32.u64 %0, t; }" : "=r"(a) : "l"(p));
    return a;
}
__device__ __forceinline__ void ldsm_x4(uint32_t (&r)[4], uint32_t addr) {
    asm volatile("ldmatrix.sync.aligned.m8n8.x4.shared.b16 {%0,%1,%2,%3}, [%4];"
        : "=r"(r[0]), "=r"(r[1]), "=r"(r[2]), "=r"(r[3]) : "r"(addr));
}
__device__ __forceinline__ void mma16816(float (&d)[4], const uint32_t (&a)[4],
                                         uint32_t b0, uint32_t b1) {
    asm volatile(
        "mma.sync.aligned.m16n8k16.row.col.f32.f16.f16.f32 "
        "{%0,%1,%2,%3}, {%4,%5,%6,%7}, {%8,%9}, {%0,%1,%2,%3};"
        : "+f"(d[0]), "+f"(d[1]), "+f"(d[2]), "+f"(d[3])
        : "r"(a[0]), "r"(a[1]), "r"(a[2]), "r"(a[3]), "r"(b0), "r"(b1));
}
__device__ __forceinline__ void cp16(uint32_t saddr, const void* g) {
    asm volatile("cp.async.cg.shared.global [%0], [%1], 16;" :: "r"(saddr), "l"(g));
}
#define CP_COMMIT() asm volatile("cp.async.commit_group;" ::: "memory")
#define CP_WAIT(N)  asm volatile("cp.async.wait_group %0;" :: "n"(N) : "memory")

__device__ __forceinline__ uint32_t pack_h2(__half a, __half b) {
    __half2 t; t.x = a; t.y = b;
    return *reinterpret_cast<uint32_t*>(&t);
}
__device__ __forceinline__ float silu(float a) { return a / (1.0f + __expf(-a)); }

// ---------------- fused conversion kernel (x, acts, wup, v1) ----------------
static constexpr size_t CB0 = (size_t)NTOK * H_ / 8;
static constexpr size_t CB1 = CB0 + (size_t)NTOK * DL_ / 8;
static constexpr size_t CB2 = CB1 + (size_t)E_ * F_ * DL_ / 8;
static constexpr size_t CB3 = CB2 + (size_t)E_ * F_ * H_ / 8;

__global__ void __launch_bounds__(256) conv_all(const float* __restrict__ x,
                                                const float* __restrict__ a,
                                                const float* __restrict__ w,
                                                const float* __restrict__ v) {
    size_t it = (size_t)blockIdx.x * 256 + threadIdx.x;
    const float* s; __half* d; size_t off;
    if      (it < CB0) { s = x; d = g_x;   off = it; }
    else if (it < CB1) { s = a; d = g_a;   off = it - CB0; }
    else if (it < CB2) { s = w; d = g_wup; off = it - CB1; }
    else               { s = v; d = g_v1;  off = it - CB2; }
    size_t i = off * 8;
    float4 v0 = *reinterpret_cast<const float4*>(s + i);
    float4 v1 = *reinterpret_cast<const float4*>(s + i + 4);
    uint4 o;
    o.x = pack_h2(__float2half_rn(v0.x), __float2half_rn(v0.y));
    o.y = pack_h2(__float2half_rn(v0.z), __float2half_rn(v0.w));
    o.z = pack_h2(__float2half_rn(v1.x), __float2half_rn(v1.y));
    o.w = pack_h2(__float2half_rn(v1.z), __float2half_rn(v1.w));
    *reinterpret_cast<uint4*>(d + i) = o;
}

// w2 [E,F,H] -> w2t [E,H,F] fp16, coalesced half2 stores
__global__ void __launch_bounds__(256) transpose_convert_w2(const float* __restrict__ w2) {
    __shared__ float tile[64][33];
    int e = blockIdx.z;
    int f0 = blockIdx.x * 64, h0 = blockIdx.y * 32;
    int tx = threadIdx.x, ty = threadIdx.y;  // 32 x 8
#pragma unroll
    for (int r = 0; r < 8; r++) {
        int fr = ty + r * 8;
        tile[fr][tx] = w2[((size_t)e * F_ + f0 + fr) * H_ + h0 + tx];
    }
    __syncthreads();
#pragma unroll
    for (int r = 0; r < 4; r++) {
        int h = ty + r * 8;
        uint32_t p = pack_h2(__float2half_rn(tile[2 * tx][h]),
                             __float2half_rn(tile[2 * tx + 1][h]));
        *reinterpret_cast<uint32_t*>(&g_w2t[((size_t)e * H_ + h0 + h) * F_ + f0 + 2 * tx]) = p;
    }
}

// ================= shared GEMM pieces: CTA 128(m) x 256(n), 512 thr, warp 32x64 =================
static constexpr int SA64 = 72;                    // row stride (fp16), 144 B
static constexpr int A_BYTES = 128 * SA64 * 2;     // 18432
static constexpr int B_BYTES = 256 * SA64 * 2;     // 36864
static constexpr int STG   = A_BYTES + B_BYTES;    // 55296
static constexpr int SMEMB = 3 * STG;              // 165888
static constexpr int NWORK = 148;

// load ROWSx64 fp16 K-major tile; 512 threads, 16B chunks
template <int ROWS>
__device__ __forceinline__ void load_rows(uint32_t sdst, const __half* __restrict__ g,
                                          int ldg, int tid) {
#pragma unroll
    for (int i = 0; i < ROWS * 8 / 512; i++) {
        int c = tid + i * 512;
        int row = c >> 3, col = (c & 7) * 8;
        cp16(sdst + (uint32_t)(row * SA64 + col) * 2, g + (size_t)row * ldg + col);
    }
}

// one K=64 stage for a 32x64 warp tile, with register-fragment double buffering:
// ldsm for the NEXT group issues before the MMAs of the current group consume theirs,
// so the ~29cyc LDS latency hides under 4 MMAs.
__device__ __forceinline__ void mma_3264(float (&acc)[2][8][4], uint32_t sb,
                                         int warp_m, int warp_n, int lane) {
    uint32_t sA = sb, sB = sb + A_BYTES;
    int lrow = lane & 15, lk = (lane >> 4) * 8;
    uint32_t abase = sA + (uint32_t)((warp_m * 32 + lrow) * SA64 + lk) * 2;
    uint32_t bbase = sB + (uint32_t)((warp_n * 64 + lrow) * SA64 + lk) * 2;
    constexpr uint32_t R16 = 16 * SA64 * 2;   // 16-row stride in bytes

    uint32_t a[2][2][4], b[2][4];
    ldsm_x4(a[0][0], abase);
    ldsm_x4(a[0][1], abase + R16);
    ldsm_x4(b[0], bbase);
#pragma unroll
    for (int ks = 0; ks < 4; ks++) {
        const int ap = ks & 1;
#pragma unroll
        for (int gj = 0; gj < 4; gj++) {
            const int bp = (ks * 4 + gj) & 1;
            // prefetch next fragments (compile-time predicates; loops fully unrolled)
            if (gj == 0 && ks < 3) ldsm_x4(a[ap ^ 1][0], abase + (ks + 1) * 32);
            if (gj == 1 && ks < 3) ldsm_x4(a[ap ^ 1][1], abase + (ks + 1) * 32 + R16);
            if (gj < 3)            ldsm_x4(b[bp ^ 1], bbase + ks * 32 + (gj + 1) * R16);
            else if (ks < 3)       ldsm_x4(b[bp ^ 1], bbase + (ks + 1) * 32);
            mma16816(acc[0][gj * 2 + 0], a[ap][0], b[bp][0], b[bp][2]);
            mma16816(acc[0][gj * 2 + 1], a[ap][0], b[bp][1], b[bp][3]);
            mma16816(acc[1][gj * 2 + 0], a[ap][1], b[bp][0], b[bp][2]);
            mma16816(acc[1][gj * 2 + 1], a[ap][1], b[bp][1], b[bp][3]);
        }
    }
}

// ================= GLU persistent: tile 128x256 =================
static constexpr int NT_GLU = (T_ / 128) * (F_ / 256) * E_;   // 1024
static constexpr int NKC_GLU = 4 + 16;                        // acts/wup then x/v1

__global__ void __launch_bounds__(512, 1) glu_kernel() {
    extern __shared__ char smem[];
    uint32_t sbase = smem_u32(smem);
    int tid = threadIdx.x, lane = tid & 31, wid = tid >> 5;
    int warp_m = wid & 3, warp_n = wid >> 2;   // 4 x 4
    int bid = blockIdx.x;

    // loader state (2 chunks ahead, flat stream across tiles)
    int lt = bid, lk = 0, ls = 0;
    const __half *LAa, *LBw, *LAx, *LBv;
    auto set_lptrs = [&](int t) {
        int e = t >> 7, r = t & 127;
        int m0 = (r >> 4) * 128, f0 = (r & 15) * 256;
        LAa = g_a   + (size_t)(e * T_ + m0) * DL_;
        LBw = g_wup + ((size_t)e * F_ + f0) * DL_;
        LAx = g_x   + (size_t)(e * T_ + m0) * H_;
        LBv = g_v1  + ((size_t)e * F_ + f0) * H_;
    };
    if (lt < NT_GLU) set_lptrs(lt);
    auto issue = [&]() {
        uint32_t sb = sbase + ls * STG;
        if (lt < NT_GLU) {
            if (lk < 4) {
                load_rows<128>(sb,           LAa + lk * 64, DL_, tid);
                load_rows<256>(sb + A_BYTES, LBw + lk * 64, DL_, tid);
            } else {
                int k2 = lk - 4;
                load_rows<128>(sb,           LAx + k2 * 64, H_, tid);
                load_rows<256>(sb + A_BYTES, LBv + k2 * 64, H_, tid);
            }
        }
        CP_COMMIT();   // empty group past end keeps wait counts uniform
        if (++ls == 3) ls = 0;
        if (++lk == NKC_GLU) { lk = 0; lt += NWORK; if (lt < NT_GLU) set_lptrs(lt); }
    };
    issue(); issue();

    int cs = 0;
    for (int ct = bid; ct < NT_GLU; ct += NWORK) {
        int e = ct >> 7, r = ct & 127;
        int m0 = (r >> 4) * 128, f0 = (r & 15) * 256;

        float acc[2][8][4];
        uint32_t x1h[2][8][2];   // packed x1 (phase A result)
#pragma unroll
        for (int i = 0; i < 2; i++)
#pragma unroll
            for (int j = 0; j < 8; j++)
#pragma unroll
                for (int k = 0; k < 4; k++) acc[i][j][k] = 0.f;

        for (int kt = 0; kt < NKC_GLU; kt++) {
            CP_WAIT(1);
            __syncthreads();
            issue();
            if (kt == 4) {
                // phase A done: pack x1 to fp16, reset acc for phase B
#pragma unroll
                for (int mi = 0; mi < 2; mi++)
#pragma unroll
                for (int nj = 0; nj < 8; nj++) {
                    x1h[mi][nj][0] = pack_h2(__float2half_rn(acc[mi][nj][0]),
                                             __float2half_rn(acc[mi][nj][1]));
                    x1h[mi][nj][1] = pack_h2(__float2half_rn(acc[mi][nj][2]),
                                             __float2half_rn(acc[mi][nj][3]));
                    acc[mi][nj][0] = 0.f; acc[mi][nj][1] = 0.f;
                    acc[mi][nj][2] = 0.f; acc[mi][nj][3] = 0.f;
                }
            }
            mma_3264(acc, sbase + cs * STG, warp_m, warp_n, lane);
            if (++cs == 3) cs = 0;
        }

        // epilogue: h = silu(x1) * acc2 -> fp16 (overlaps next tile's loads)
        int gid = lane >> 2, q = lane & 3;
#pragma unroll
        for (int mi = 0; mi < 2; mi++)
#pragma unroll
        for (int nj = 0; nj < 8; nj++) {
            int m = m0 + warp_m * 32 + mi * 16 + gid;
            int n = f0 + warp_n * 64 + nj * 8 + q * 2;
            __half2 p0 = *reinterpret_cast<__half2*>(&x1h[mi][nj][0]);
            __half2 p1 = *reinterpret_cast<__half2*>(&x1h[mi][nj][1]);
            float s0 = silu(__half2float(p0.x)) * acc[mi][nj][0];
            float s1 = silu(__half2float(p0.y)) * acc[mi][nj][1];
            float s2 = silu(__half2float(p1.x)) * acc[mi][nj][2];
            float s3 = silu(__half2float(p1.y)) * acc[mi][nj][3];
            size_t off0 = ((size_t)(e * T_ + m)) * F_ + n;
            size_t off1 = ((size_t)(e * T_ + m + 8)) * F_ + n;
            *reinterpret_cast<uint32_t*>(g_h + off0) = pack_h2(__float2half_rn(s0), __float2half_rn(s1));
            *reinterpret_cast<uint32_t*>(g_h + off1) = pack_h2(__float2half_rn(s2), __float2half_rn(s3));
        }
    }
}

// ================= GEMM3 persistent: tile 128x256, K=4096 =================
static constexpr int NT_G3  = (T_ / 128) * (H_ / 256) * E_;  // 256
static constexpr int NKC_G3 = F_ / 64;                       // 64

__global__ void __launch_bounds__(512, 1) gemm3_kernel(float* __restrict__ out) {
    extern __shared__ char smem[];
    uint32_t sbase = smem_u32(smem);
    int tid = threadIdx.x, lane = tid & 31, wid = tid >> 5;
    int warp_m = wid & 3, warp_n = wid >> 2;   // 4 x 4
    int bid = blockIdx.x;

    int lt = bid, lk = 0, ls = 0;
    const __half *LA, *LB;
    auto set_lptrs = [&](int t) {
        int e = t >> 5, r = t & 31;
        int m0 = (r >> 2) * 128, n0 = (r & 3) * 256;
        LA = g_h   + (size_t)(e * T_ + m0) * F_;
        LB = g_w2t + ((size_t)e * H_ + n0) * F_;
    };
    if (lt < NT_G3) set_lptrs(lt);
    auto issue = [&]() {
        uint32_t sb = sbase + ls * STG;
        if (lt < NT_G3) {
            load_rows<128>(sb,           LA + lk * 64, F_, tid);
            load_rows<256>(sb + A_BYTES, LB + lk * 64, F_, tid);
        }
        CP_COMMIT();
        if (++ls == 3) ls = 0;
        if (++lk == NKC_G3) { lk = 0; lt += NWORK; if (lt < NT_G3) set_lptrs(lt); }
    };
    issue(); issue();

    int cs = 0;
    for (int ct = bid; ct < NT_G3; ct += NWORK) {
        int e = ct >> 5, r = ct & 31;
        int m0 = (r >> 2) * 128, n0 = (r & 3) * 256;

        float acc[2][8][4];
#pragma unroll
        for (int i = 0; i < 2; i++)
#pragma unroll
            for (int j = 0; j < 8; j++)
#pragma unroll
                for (int k = 0; k < 4; k++) acc[i][j][k] = 0.f;

        for (int kt = 0; kt < NKC_G3; kt++) {
            CP_WAIT(1);
            __syncthreads();
            issue();
            mma_3264(acc, sbase + cs * STG, warp_m, warp_n, lane);
            if (++cs == 3) cs = 0;
        }

        int gid = lane >> 2, q = lane & 3;
#pragma unroll
        for (int mi = 0; mi < 2; mi++)
#pragma unroll
        for (int nj = 0; nj < 8; nj++) {
            int m = m0 + warp_m * 32 + mi * 16 + gid;
            int n = n0 + warp_n * 64 + nj * 8 + q * 2;
            size_t off0 = ((size_t)(e * T_ + m)) * H_ + n;
            size_t off1 = ((size_t)(e * T_ + m + 8)) * H_ + n;
            *reinterpret_cast<float2*>(out + off0) = make_float2(acc[mi][nj][0], acc[mi][nj][1]);
            *reinterpret_cast<float2*>(out + off1) = make_float2(acc[mi][nj][2], acc[mi][nj][3]);
        }
    }
}

// ---------------- launch ----------------
extern "C" void kernel_launch(void* const* d_in, const int* in_sizes, int n_in,
                              void* d_out, int out_size) {
    const float* x    = (const float*)d_in[0];  // [8192, 1024]
    const float* acts = (const float*)d_in[1];  // [8192, 256]
    const float* wup  = (const float*)d_in[2];  // [8, 4096, 256]
    const float* v1   = (const float*)d_in[3];  // [8, 4096, 1024]
    const float* w2   = (const float*)d_in[4];  // [8, 4096, 1024]
    float* out = (float*)d_out;                 // [8192, 1024]

    cudaFuncSetAttribute(glu_kernel,   cudaFuncAttributeMaxDynamicSharedMemorySize, SMEMB);
    cudaFuncSetAttribute(gemm3_kernel, cudaFuncAttributeMaxDynamicSharedMemorySize, SMEMB);

    conv_all<<<(int)(CB3 / 256), 256>>>(x, acts, wup, v1);
    {
        dim3 tg(F_ / 64, H_ / 32, E_);
        transpose_convert_w2<<<tg, dim3(32, 8)>>>(w2);
    }
    glu_kernel<<<NWORK, 512, SMEMB>>>();
    gemm3_kernel<<<NWORK, 512, SMEMB>>>(out);
}